// round 5
// baseline (speedup 1.0000x reference)
#include <cuda_runtime.h>
#include <math.h>

#define NB   1024
#define NR   2336
#define NK   2
// Cin = 4, Cout = 16 (fixed)

// Scratch: u_ji[b][k][r][o] stored as float4 quads: index ((b*NK+k)*NR + r)*4 + oq
__device__ float4 g_uji[(size_t)NB * NK * NR * 4];
__device__ float  g_cls[NB * NK];

// ---------------------------------------------------------------------------
// Kernel A: projection u_ji[b,k,r,o] = sum_i u[b,r,i] * W[k,r,i,o]
// Grid: (73 route-chunks, 2 k). Block: 128 = 32 routes x 4 o-quads.
// W chunk lives in registers; loop over all b so W is read ~once from HBM/L2.
// ---------------------------------------------------------------------------
__global__ void __launch_bounds__(128) caps_proj_kernel(
    const float4* __restrict__ u4,   // u as float4: [b*NR + r]
    const float4* __restrict__ W4)   // W as float4: [((k*NR+r)*4 + i)*4 + oq]
{
    const int rl = threadIdx.x >> 2;       // 0..31
    const int oq = threadIdx.x & 3;        // 0..3
    const int k  = blockIdx.y;
    const int r  = blockIdx.x * 32 + rl;   // < 2336 always (73*32 = 2336)

    const size_t wbase = ((size_t)(k * NR + r) * 4) * 4 + oq;
    const float4 w0 = W4[wbase + 0];
    const float4 w1 = W4[wbase + 4];
    const float4 w2 = W4[wbase + 8];
    const float4 w3 = W4[wbase + 12];

    size_t oidx = ((size_t)k * NR + r) * 4 + oq;
    const size_t ostride = (size_t)NK * NR * 4;

#pragma unroll 4
    for (int b = 0; b < NB; b++) {
        float4 uu = __ldg(&u4[(size_t)b * NR + r]);
        float4 o;
        o.x = fmaf(uu.x, w0.x, fmaf(uu.y, w1.x, fmaf(uu.z, w2.x, uu.w * w3.x)));
        o.y = fmaf(uu.x, w0.y, fmaf(uu.y, w1.y, fmaf(uu.z, w2.y, uu.w * w3.y)));
        o.z = fmaf(uu.x, w0.z, fmaf(uu.y, w1.z, fmaf(uu.z, w2.z, uu.w * w3.z)));
        o.w = fmaf(uu.x, w0.w, fmaf(uu.y, w1.w, fmaf(uu.z, w2.w, uu.w * w3.w)));
        g_uji[oidx] = o;
        oidx += ostride;
    }
}

// ---------------------------------------------------------------------------
// Kernel B: routing. One CTA per (b,k). u_ji tile resident in smem.
// ---------------------------------------------------------------------------
// smem layout (floats):
#define OFF_BS   37376      // logits b[r], 2336 floats
#define OFF_RED  39712      // 32 x float4 per-warp/per-q partials
#define OFF_ZRED 39840      // 8 floats
#define OFF_V    39848      // 4 x float4 (v vector)
#define OFF_CLS  39864      // 1 float
#define SMEM_FLOATS 39872
#define SMEM_BYTES (SMEM_FLOATS * 4)   // 159488

__device__ __forceinline__ void squash_store(const float4* red, float4* v4s,
                                             float* clsp, float cn)
{
    float s[16];
#pragma unroll
    for (int qq = 0; qq < 4; qq++) {
        float4 a = red[qq];
        s[qq*4+0] = a.x * cn; s[qq*4+1] = a.y * cn;
        s[qq*4+2] = a.z * cn; s[qq*4+3] = a.w * cn;
    }
    float n = 0.f;
#pragma unroll
    for (int o = 0; o < 16; o++) n += s[o] * s[o];
    // squash: v = (n/(1+n)) * s / sqrt(n);  |v| = n/(1+n)
    float f = n / ((1.f + n) * sqrtf(fmaxf(n, 1e-30f)));
#pragma unroll
    for (int qq = 0; qq < 4; qq++)
        v4s[qq] = make_float4(f*s[qq*4+0], f*s[qq*4+1], f*s[qq*4+2], f*s[qq*4+3]);
    *clsp = n / (1.f + n);
}

#define XOR_RED4(a, off) do { \
    a.x += __shfl_xor_sync(0xffffffffu, a.x, off); \
    a.y += __shfl_xor_sync(0xffffffffu, a.y, off); \
    a.z += __shfl_xor_sync(0xffffffffu, a.z, off); \
    a.w += __shfl_xor_sync(0xffffffffu, a.w, off); } while (0)

__global__ void __launch_bounds__(256) caps_route_kernel()
{
    extern __shared__ float sm[];
    float4* uji  = (float4*)sm;                 // [NR*4] float4 quads
    float*  bs   = sm + OFF_BS;
    float4* red  = (float4*)(sm + OFF_RED);
    float*  zred = sm + OFF_ZRED;
    float4* v4s  = (float4*)(sm + OFF_V);

    const int t = threadIdx.x;
    const int lane = t & 31, warp = t >> 5;
    const int q = t & 3;                        // o-quad this thread owns
    const int g = t >> 2;                       // route group 0..63
    const int bid = blockIdx.x;                 // = b*2 + k

    // --- Phase 1: stage u_ji into smem, fused with sweep-1 (uniform c = 1/R) ---
    // i = t + 256*j  =>  q_of_i = t&3 (constant), r_of_i = g + 64*j  (matches sweep layout)
    const float4* src = g_uji + (size_t)bid * (NR * 4);
    float4 acc = make_float4(0.f, 0.f, 0.f, 0.f);
    for (int i = t; i < NR * 4; i += 256) {
        float4 v = __ldg(&src[i]);
        uji[i] = v;
        acc.x += v.x; acc.y += v.y; acc.z += v.z; acc.w += v.w;
    }

    // reduce acc across threads sharing q
    XOR_RED4(acc, 4); XOR_RED4(acc, 8); XOR_RED4(acc, 16);
    if (lane < 4) red[warp * 4 + lane] = acc;
    __syncthreads();
    if (warp == 0) {
        float4 a = red[lane];
        XOR_RED4(a, 4); XOR_RED4(a, 8); XOR_RED4(a, 16);
        if (lane < 4) red[lane] = a;
    }
    __syncthreads();
    if (t == 0) squash_store(red, v4s, sm + OFF_CLS, 1.f / (float)NR);
    __syncthreads();

    // --- Phase 2: two fused (b-update + online softmax s-sweep) iterations ---
    for (int it = 0; it < 2; it++) {
        const float4 v = v4s[q];
        float4 an = make_float4(0.f, 0.f, 0.f, 0.f);
        float  Z  = 0.f;
        for (int rr = 0; rr < 37; rr++) {
            int r = rr * 64 + g;
            if (r < NR) {           // whole warps diverge together (g range per warp)
                float4 uv = uji[r * 4 + q];
                float d = uv.x*v.x + uv.y*v.y + uv.z*v.z + uv.w*v.w;
                d += __shfl_xor_sync(0xffffffffu, d, 1);
                d += __shfl_xor_sync(0xffffffffu, d, 2);   // full 16-dot
                float bn;
                if (it == 0) { bn = d; if (q == 0) bs[r] = bn; }
                else         { bn = bs[r] + d; }
                float e = expf(bn);                        // logits bounded, no max-shift
                Z += e;
                an.x = fmaf(e, uv.x, an.x);
                an.y = fmaf(e, uv.y, an.y);
                an.z = fmaf(e, uv.z, an.z);
                an.w = fmaf(e, uv.w, an.w);
            }
        }
        XOR_RED4(an, 4); XOR_RED4(an, 8); XOR_RED4(an, 16);
        Z += __shfl_xor_sync(0xffffffffu, Z, 1);
        Z += __shfl_xor_sync(0xffffffffu, Z, 2);
        Z += __shfl_xor_sync(0xffffffffu, Z, 4);
        Z += __shfl_xor_sync(0xffffffffu, Z, 8);
        Z += __shfl_xor_sync(0xffffffffu, Z, 16);
        if (lane < 4)  red[warp * 4 + lane] = an;
        if (lane == 0) zred[warp] = Z;
        __syncthreads();
        if (warp == 0) {
            float4 a = red[lane];
            XOR_RED4(a, 4); XOR_RED4(a, 8); XOR_RED4(a, 16);
            if (lane < 4) red[lane] = a;
        }
        __syncthreads();
        if (t == 0) {
            float Zt = 0.f;
            for (int w = 0; w < 8; w++) Zt += zred[w];
            Zt *= 0.25f;   // each e counted by 4 q-threads
            squash_store(red, v4s, sm + OFF_CLS, 1.f / Zt);
        }
        __syncthreads();
    }

    if (t == 0) g_cls[bid] = sm[OFF_CLS];
}

// ---------------------------------------------------------------------------
// Kernel C: final softmax over K=2 classes per batch
// ---------------------------------------------------------------------------
__global__ void caps_softmax_kernel(float* __restrict__ out)
{
    int b = blockIdx.x * blockDim.x + threadIdx.x;
    if (b < NB) {
        float c0 = g_cls[2*b], c1 = g_cls[2*b + 1];
        float m  = fmaxf(c0, c1);
        float e0 = expf(c0 - m), e1 = expf(c1 - m);
        float inv = 1.f / (e0 + e1);
        out[2*b]     = e0 * inv;
        out[2*b + 1] = e1 * inv;
    }
}

// ---------------------------------------------------------------------------
extern "C" void kernel_launch(void* const* d_in, const int* in_sizes, int n_in,
                              void* d_out, int out_size)
{
    const float4* u4 = (const float4*)d_in[0];   // u: [1024,2336,4] f32
    const float4* W4 = (const float4*)d_in[1];   // W: [2,2336,4,16] f32
    (void)in_sizes; (void)n_in; (void)out_size;

    cudaFuncSetAttribute(caps_route_kernel,
                         cudaFuncAttributeMaxDynamicSharedMemorySize, SMEM_BYTES);

    caps_proj_kernel<<<dim3(73, 2), 128>>>(u4, W4);
    caps_route_kernel<<<NB * NK, 256, SMEM_BYTES>>>();
    caps_softmax_kernel<<<(NB + 255) / 256, 256>>>((float*)d_out);
}

// round 6
// speedup vs baseline: 1.0002x; 1.0002x over previous
#include <cuda_runtime.h>
#include <math.h>

#define NB   1024
#define NR   2336
#define NK   2
// Cin = 4, Cout = 16 (fixed)

// Scratch: u_ji[b][k][r][o] stored as float4 quads: index ((b*NK+k)*NR + r)*4 + oq
__device__ float4 g_uji[(size_t)NB * NK * NR * 4];
__device__ float  g_cls[NB * NK];

// ---------------------------------------------------------------------------
// Kernel A: projection u_ji[b,k,r,o] = sum_i u[b,r,i] * W[k,r,i,o]
// Grid: (73 route-chunks, 2 k). Block: 128 = 32 routes x 4 o-quads.
// W chunk lives in registers; loop over all b so W is read ~once from HBM/L2.
// ---------------------------------------------------------------------------
__global__ void __launch_bounds__(128) caps_proj_kernel(
    const float4* __restrict__ u4,   // u as float4: [b*NR + r]
    const float4* __restrict__ W4)   // W as float4: [((k*NR+r)*4 + i)*4 + oq]
{
    const int rl = threadIdx.x >> 2;       // 0..31
    const int oq = threadIdx.x & 3;        // 0..3
    const int k  = blockIdx.y;
    const int r  = blockIdx.x * 32 + rl;   // < 2336 always (73*32 = 2336)

    const size_t wbase = ((size_t)(k * NR + r) * 4) * 4 + oq;
    const float4 w0 = W4[wbase + 0];
    const float4 w1 = W4[wbase + 4];
    const float4 w2 = W4[wbase + 8];
    const float4 w3 = W4[wbase + 12];

    size_t oidx = ((size_t)k * NR + r) * 4 + oq;
    const size_t ostride = (size_t)NK * NR * 4;

#pragma unroll 4
    for (int b = 0; b < NB; b++) {
        float4 uu = __ldg(&u4[(size_t)b * NR + r]);
        float4 o;
        o.x = fmaf(uu.x, w0.x, fmaf(uu.y, w1.x, fmaf(uu.z, w2.x, uu.w * w3.x)));
        o.y = fmaf(uu.x, w0.y, fmaf(uu.y, w1.y, fmaf(uu.z, w2.y, uu.w * w3.y)));
        o.z = fmaf(uu.x, w0.z, fmaf(uu.y, w1.z, fmaf(uu.z, w2.z, uu.w * w3.z)));
        o.w = fmaf(uu.x, w0.w, fmaf(uu.y, w1.w, fmaf(uu.z, w2.w, uu.w * w3.w)));
        g_uji[oidx] = o;
        oidx += ostride;
    }
}

// ---------------------------------------------------------------------------
// Kernel B: routing. One CTA per (b,k). u_ji tile resident in smem.
// ---------------------------------------------------------------------------
// smem layout (floats):
#define OFF_BS   37376      // logits b[r], 2336 floats
#define OFF_RED  39712      // 32 x float4 per-warp/per-q partials
#define OFF_ZRED 39840      // 8 floats
#define OFF_V    39848      // 4 x float4 (v vector)
#define OFF_CLS  39864      // 1 float
#define SMEM_FLOATS 39872
#define SMEM_BYTES (SMEM_FLOATS * 4)   // 159488

__device__ __forceinline__ void squash_store(const float4* red, float4* v4s,
                                             float* clsp, float cn)
{
    float s[16];
#pragma unroll
    for (int qq = 0; qq < 4; qq++) {
        float4 a = red[qq];
        s[qq*4+0] = a.x * cn; s[qq*4+1] = a.y * cn;
        s[qq*4+2] = a.z * cn; s[qq*4+3] = a.w * cn;
    }
    float n = 0.f;
#pragma unroll
    for (int o = 0; o < 16; o++) n += s[o] * s[o];
    // squash: v = (n/(1+n)) * s / sqrt(n);  |v| = n/(1+n)
    float f = n / ((1.f + n) * sqrtf(fmaxf(n, 1e-30f)));
#pragma unroll
    for (int qq = 0; qq < 4; qq++)
        v4s[qq] = make_float4(f*s[qq*4+0], f*s[qq*4+1], f*s[qq*4+2], f*s[qq*4+3]);
    *clsp = n / (1.f + n);
}

#define XOR_RED4(a, off) do { \
    a.x += __shfl_xor_sync(0xffffffffu, a.x, off); \
    a.y += __shfl_xor_sync(0xffffffffu, a.y, off); \
    a.z += __shfl_xor_sync(0xffffffffu, a.z, off); \
    a.w += __shfl_xor_sync(0xffffffffu, a.w, off); } while (0)

__global__ void __launch_bounds__(256) caps_route_kernel()
{
    extern __shared__ float sm[];
    float4* uji  = (float4*)sm;                 // [NR*4] float4 quads
    float*  bs   = sm + OFF_BS;
    float4* red  = (float4*)(sm + OFF_RED);
    float*  zred = sm + OFF_ZRED;
    float4* v4s  = (float4*)(sm + OFF_V);

    const int t = threadIdx.x;
    const int lane = t & 31, warp = t >> 5;
    const int q = t & 3;                        // o-quad this thread owns
    const int g = t >> 2;                       // route group 0..63
    const int bid = blockIdx.x;                 // = b*2 + k

    // --- Phase 1: stage u_ji into smem, fused with sweep-1 (uniform c = 1/R) ---
    // i = t + 256*j  =>  q_of_i = t&3 (constant), r_of_i = g + 64*j  (matches sweep layout)
    const float4* src = g_uji + (size_t)bid * (NR * 4);
    float4 acc = make_float4(0.f, 0.f, 0.f, 0.f);
    for (int i = t; i < NR * 4; i += 256) {
        float4 v = __ldg(&src[i]);
        uji[i] = v;
        acc.x += v.x; acc.y += v.y; acc.z += v.z; acc.w += v.w;
    }

    // reduce acc across threads sharing q
    XOR_RED4(acc, 4); XOR_RED4(acc, 8); XOR_RED4(acc, 16);
    if (lane < 4) red[warp * 4 + lane] = acc;
    __syncthreads();
    if (warp == 0) {
        float4 a = red[lane];
        XOR_RED4(a, 4); XOR_RED4(a, 8); XOR_RED4(a, 16);
        if (lane < 4) red[lane] = a;
    }
    __syncthreads();
    if (t == 0) squash_store(red, v4s, sm + OFF_CLS, 1.f / (float)NR);
    __syncthreads();

    // --- Phase 2: two fused (b-update + online softmax s-sweep) iterations ---
    for (int it = 0; it < 2; it++) {
        const float4 v = v4s[q];
        float4 an = make_float4(0.f, 0.f, 0.f, 0.f);
        float  Z  = 0.f;
        for (int rr = 0; rr < 37; rr++) {
            int r = rr * 64 + g;
            if (r < NR) {           // whole warps diverge together (g range per warp)
                float4 uv = uji[r * 4 + q];
                float d = uv.x*v.x + uv.y*v.y + uv.z*v.z + uv.w*v.w;
                d += __shfl_xor_sync(0xffffffffu, d, 1);
                d += __shfl_xor_sync(0xffffffffu, d, 2);   // full 16-dot
                float bn;
                if (it == 0) { bn = d; if (q == 0) bs[r] = bn; }
                else         { bn = bs[r] + d; }
                float e = expf(bn);                        // logits bounded, no max-shift
                Z += e;
                an.x = fmaf(e, uv.x, an.x);
                an.y = fmaf(e, uv.y, an.y);
                an.z = fmaf(e, uv.z, an.z);
                an.w = fmaf(e, uv.w, an.w);
            }
        }
        XOR_RED4(an, 4); XOR_RED4(an, 8); XOR_RED4(an, 16);
        Z += __shfl_xor_sync(0xffffffffu, Z, 1);
        Z += __shfl_xor_sync(0xffffffffu, Z, 2);
        Z += __shfl_xor_sync(0xffffffffu, Z, 4);
        Z += __shfl_xor_sync(0xffffffffu, Z, 8);
        Z += __shfl_xor_sync(0xffffffffu, Z, 16);
        if (lane < 4)  red[warp * 4 + lane] = an;
        if (lane == 0) zred[warp] = Z;
        __syncthreads();
        if (warp == 0) {
            float4 a = red[lane];
            XOR_RED4(a, 4); XOR_RED4(a, 8); XOR_RED4(a, 16);
            if (lane < 4) red[lane] = a;
        }
        __syncthreads();
        if (t == 0) {
            float Zt = 0.f;
            for (int w = 0; w < 8; w++) Zt += zred[w];
            Zt *= 0.25f;   // each e counted by 4 q-threads
            squash_store(red, v4s, sm + OFF_CLS, 1.f / Zt);
        }
        __syncthreads();
    }

    if (t == 0) g_cls[bid] = sm[OFF_CLS];
}

// ---------------------------------------------------------------------------
// Kernel C: final softmax over K=2 classes per batch
// ---------------------------------------------------------------------------
__global__ void caps_softmax_kernel(float* __restrict__ out)
{
    int b = blockIdx.x * blockDim.x + threadIdx.x;
    if (b < NB) {
        float c0 = g_cls[2*b], c1 = g_cls[2*b + 1];
        float m  = fmaxf(c0, c1);
        float e0 = expf(c0 - m), e1 = expf(c1 - m);
        float inv = 1.f / (e0 + e1);
        out[2*b]     = e0 * inv;
        out[2*b + 1] = e1 * inv;
    }
}

// ---------------------------------------------------------------------------
extern "C" void kernel_launch(void* const* d_in, const int* in_sizes, int n_in,
                              void* d_out, int out_size)
{
    const float4* u4 = (const float4*)d_in[0];   // u: [1024,2336,4] f32
    const float4* W4 = (const float4*)d_in[1];   // W: [2,2336,4,16] f32
    (void)in_sizes; (void)n_in; (void)out_size;

    cudaFuncSetAttribute(caps_route_kernel,
                         cudaFuncAttributeMaxDynamicSharedMemorySize, SMEM_BYTES);

    caps_proj_kernel<<<dim3(73, 2), 128>>>(u4, W4);
    caps_route_kernel<<<NB * NK, 256, SMEM_BYTES>>>();
    caps_softmax_kernel<<<(NB + 255) / 256, 256>>>((float*)d_out);
}

// round 7
// speedup vs baseline: 1.0059x; 1.0058x over previous
#include <cuda_runtime.h>
#include <math.h>

#define NB   1024
#define NR   2336
#define NK   2
// Cin = 4, Cout = 16 (fixed)

// Scratch: u_ji[b][k][r][o] stored as float4 quads: index ((b*NK+k)*NR + r)*4 + oq
__device__ float4 g_uji[(size_t)NB * NK * NR * 4];
__device__ float  g_cls[NB * NK];

// ---------------------------------------------------------------------------
// Kernel A: projection u_ji[b,k,r,o] = sum_i u[b,r,i] * W[k,r,i,o]
// Grid: (73 route-chunks, 2 k). Block: 128 = 32 routes x 4 o-quads.
// W chunk lives in registers; loop over all b so W is read ~once from HBM/L2.
// ---------------------------------------------------------------------------
__global__ void __launch_bounds__(128) caps_proj_kernel(
    const float4* __restrict__ u4,   // u as float4: [b*NR + r]
    const float4* __restrict__ W4)   // W as float4: [((k*NR+r)*4 + i)*4 + oq]
{
    const int rl = threadIdx.x >> 2;       // 0..31
    const int oq = threadIdx.x & 3;        // 0..3
    const int k  = blockIdx.y;
    const int r  = blockIdx.x * 32 + rl;   // < 2336 always (73*32 = 2336)

    const size_t wbase = ((size_t)(k * NR + r) * 4) * 4 + oq;
    const float4 w0 = W4[wbase + 0];
    const float4 w1 = W4[wbase + 4];
    const float4 w2 = W4[wbase + 8];
    const float4 w3 = W4[wbase + 12];

    size_t oidx = ((size_t)k * NR + r) * 4 + oq;
    const size_t ostride = (size_t)NK * NR * 4;

#pragma unroll 4
    for (int b = 0; b < NB; b++) {
        float4 uu = __ldg(&u4[(size_t)b * NR + r]);
        float4 o;
        o.x = fmaf(uu.x, w0.x, fmaf(uu.y, w1.x, fmaf(uu.z, w2.x, uu.w * w3.x)));
        o.y = fmaf(uu.x, w0.y, fmaf(uu.y, w1.y, fmaf(uu.z, w2.y, uu.w * w3.y)));
        o.z = fmaf(uu.x, w0.z, fmaf(uu.y, w1.z, fmaf(uu.z, w2.z, uu.w * w3.z)));
        o.w = fmaf(uu.x, w0.w, fmaf(uu.y, w1.w, fmaf(uu.z, w2.w, uu.w * w3.w)));
        g_uji[oidx] = o;
        oidx += ostride;
    }
}

// ---------------------------------------------------------------------------
// Kernel B: routing. One CTA per (b,k). u_ji tile resident in smem.
// ---------------------------------------------------------------------------
// smem layout (floats):
#define OFF_BS   37376      // logits b[r], 2336 floats
#define OFF_RED  39712      // 32 x float4 per-warp/per-q partials
#define OFF_ZRED 39840      // 8 floats
#define OFF_V    39848      // 4 x float4 (v vector)
#define OFF_CLS  39864      // 1 float
#define SMEM_FLOATS 39872
#define SMEM_BYTES (SMEM_FLOATS * 4)   // 159488

__device__ __forceinline__ void squash_store(const float4* red, float4* v4s,
                                             float* clsp, float cn)
{
    float s[16];
#pragma unroll
    for (int qq = 0; qq < 4; qq++) {
        float4 a = red[qq];
        s[qq*4+0] = a.x * cn; s[qq*4+1] = a.y * cn;
        s[qq*4+2] = a.z * cn; s[qq*4+3] = a.w * cn;
    }
    float n = 0.f;
#pragma unroll
    for (int o = 0; o < 16; o++) n += s[o] * s[o];
    // squash: v = (n/(1+n)) * s / sqrt(n);  |v| = n/(1+n)
    float f = n / ((1.f + n) * sqrtf(fmaxf(n, 1e-30f)));
#pragma unroll
    for (int qq = 0; qq < 4; qq++)
        v4s[qq] = make_float4(f*s[qq*4+0], f*s[qq*4+1], f*s[qq*4+2], f*s[qq*4+3]);
    *clsp = n / (1.f + n);
}

#define XOR_RED4(a, off) do { \
    a.x += __shfl_xor_sync(0xffffffffu, a.x, off); \
    a.y += __shfl_xor_sync(0xffffffffu, a.y, off); \
    a.z += __shfl_xor_sync(0xffffffffu, a.z, off); \
    a.w += __shfl_xor_sync(0xffffffffu, a.w, off); } while (0)

__global__ void __launch_bounds__(256) caps_route_kernel()
{
    extern __shared__ float sm[];
    float4* uji  = (float4*)sm;                 // [NR*4] float4 quads
    float*  bs   = sm + OFF_BS;
    float4* red  = (float4*)(sm + OFF_RED);
    float*  zred = sm + OFF_ZRED;
    float4* v4s  = (float4*)(sm + OFF_V);

    const int t = threadIdx.x;
    const int lane = t & 31, warp = t >> 5;
    const int q = t & 3;                        // o-quad this thread owns
    const int g = t >> 2;                       // route group 0..63
    const int bid = blockIdx.x;                 // = b*2 + k

    // --- Phase 1: stage u_ji into smem, fused with sweep-1 (uniform c = 1/R) ---
    // i = t + 256*j  =>  q_of_i = t&3 (constant), r_of_i = g + 64*j  (matches sweep layout)
    const float4* src = g_uji + (size_t)bid * (NR * 4);
    float4 acc = make_float4(0.f, 0.f, 0.f, 0.f);
    for (int i = t; i < NR * 4; i += 256) {
        float4 v = __ldg(&src[i]);
        uji[i] = v;
        acc.x += v.x; acc.y += v.y; acc.z += v.z; acc.w += v.w;
    }

    // reduce acc across threads sharing q
    XOR_RED4(acc, 4); XOR_RED4(acc, 8); XOR_RED4(acc, 16);
    if (lane < 4) red[warp * 4 + lane] = acc;
    __syncthreads();
    if (warp == 0) {
        float4 a = red[lane];
        XOR_RED4(a, 4); XOR_RED4(a, 8); XOR_RED4(a, 16);
        if (lane < 4) red[lane] = a;
    }
    __syncthreads();
    if (t == 0) squash_store(red, v4s, sm + OFF_CLS, 1.f / (float)NR);
    __syncthreads();

    // --- Phase 2: two fused (b-update + online softmax s-sweep) iterations ---
    for (int it = 0; it < 2; it++) {
        const float4 v = v4s[q];
        float4 an = make_float4(0.f, 0.f, 0.f, 0.f);
        float  Z  = 0.f;
        for (int rr = 0; rr < 37; rr++) {
            int r = rr * 64 + g;
            if (r < NR) {           // whole warps diverge together (g range per warp)
                float4 uv = uji[r * 4 + q];
                float d = uv.x*v.x + uv.y*v.y + uv.z*v.z + uv.w*v.w;
                d += __shfl_xor_sync(0xffffffffu, d, 1);
                d += __shfl_xor_sync(0xffffffffu, d, 2);   // full 16-dot
                float bn;
                if (it == 0) { bn = d; if (q == 0) bs[r] = bn; }
                else         { bn = bs[r] + d; }
                float e = expf(bn);                        // logits bounded, no max-shift
                Z += e;
                an.x = fmaf(e, uv.x, an.x);
                an.y = fmaf(e, uv.y, an.y);
                an.z = fmaf(e, uv.z, an.z);
                an.w = fmaf(e, uv.w, an.w);
            }
        }
        XOR_RED4(an, 4); XOR_RED4(an, 8); XOR_RED4(an, 16);
        Z += __shfl_xor_sync(0xffffffffu, Z, 1);
        Z += __shfl_xor_sync(0xffffffffu, Z, 2);
        Z += __shfl_xor_sync(0xffffffffu, Z, 4);
        Z += __shfl_xor_sync(0xffffffffu, Z, 8);
        Z += __shfl_xor_sync(0xffffffffu, Z, 16);
        if (lane < 4)  red[warp * 4 + lane] = an;
        if (lane == 0) zred[warp] = Z;
        __syncthreads();
        if (warp == 0) {
            float4 a = red[lane];
            XOR_RED4(a, 4); XOR_RED4(a, 8); XOR_RED4(a, 16);
            if (lane < 4) red[lane] = a;
        }
        __syncthreads();
        if (t == 0) {
            float Zt = 0.f;
            for (int w = 0; w < 8; w++) Zt += zred[w];
            Zt *= 0.25f;   // each e counted by 4 q-threads
            squash_store(red, v4s, sm + OFF_CLS, 1.f / Zt);
        }
        __syncthreads();
    }

    if (t == 0) g_cls[bid] = sm[OFF_CLS];
}

// ---------------------------------------------------------------------------
// Kernel C: final softmax over K=2 classes per batch
// ---------------------------------------------------------------------------
__global__ void caps_softmax_kernel(float* __restrict__ out)
{
    int b = blockIdx.x * blockDim.x + threadIdx.x;
    if (b < NB) {
        float c0 = g_cls[2*b], c1 = g_cls[2*b + 1];
        float m  = fmaxf(c0, c1);
        float e0 = expf(c0 - m), e1 = expf(c1 - m);
        float inv = 1.f / (e0 + e1);
        out[2*b]     = e0 * inv;
        out[2*b + 1] = e1 * inv;
    }
}

// ---------------------------------------------------------------------------
extern "C" void kernel_launch(void* const* d_in, const int* in_sizes, int n_in,
                              void* d_out, int out_size)
{
    const float4* u4 = (const float4*)d_in[0];   // u: [1024,2336,4] f32
    const float4* W4 = (const float4*)d_in[1];   // W: [2,2336,4,16] f32
    (void)in_sizes; (void)n_in; (void)out_size;

    cudaFuncSetAttribute(caps_route_kernel,
                         cudaFuncAttributeMaxDynamicSharedMemorySize, SMEM_BYTES);

    caps_proj_kernel<<<dim3(73, 2), 128>>>(u4, W4);
    caps_route_kernel<<<NB * NK, 256, SMEM_BYTES>>>();
    caps_softmax_kernel<<<(NB + 255) / 256, 256>>>((float*)d_out);
}

// round 8
// speedup vs baseline: 3.3703x; 3.3504x over previous
#include <cuda_runtime.h>
#include <math.h>

#define NB   1024
#define NR   2336
#define NK   2
// Cin = 4, Cout = 16 (fixed)

__device__ float g_cls[NB * NK];

// ---------------------------------------------------------------------------
// Fused kernel: projection + routing. One CTA per (b,k); u_ji computed from
// u and W (L2-resident) straight into smem quad-planes. No global scratch.
// ---------------------------------------------------------------------------
// smem layout (floats):
//   4 quad-planes of PSTRIDE float4 each: plane[q][r] = u_ji[r][4q..4q+3]
//   PSTRIDE = 2338 float4 => plane-to-plane offset = 9352 words = 8 (mod 32)
//   banks: store pattern (lanes = 2 routes x 4 quads per 8-lane phase) and
//   load pattern (lanes = 8 consecutive routes, fixed quad) both conflict-free.
#define PSTRIDE  2338
#define OFF_BS   (4 * PSTRIDE * 4)          // 37408 : logits b[r], NR floats
#define OFF_RED  (OFF_BS + NR)              // 39744 : 32 x float4 partials
#define OFF_ZRED (OFF_RED + 128)            // 39872 : 8 floats
#define OFF_V    (OFF_ZRED + 8)             // 39880 : 4 x float4 (v vector)
#define OFF_CLS  (OFF_V + 16)               // 39896 : 1 float
#define SMEM_FLOATS (OFF_CLS + 4)
#define SMEM_BYTES  (SMEM_FLOATS * 4)       // 159600 B -> 1 CTA/SM

__device__ __forceinline__ void squash_store(const float4* red, float4* v4s,
                                             float* clsp, float cn)
{
    float s[16];
#pragma unroll
    for (int qq = 0; qq < 4; qq++) {
        float4 a = red[qq];
        s[qq*4+0] = a.x * cn; s[qq*4+1] = a.y * cn;
        s[qq*4+2] = a.z * cn; s[qq*4+3] = a.w * cn;
    }
    float n = 0.f;
#pragma unroll
    for (int o = 0; o < 16; o++) n += s[o] * s[o];
    // squash: v = (n/(1+n)) * s / sqrt(n);  |v| = n/(1+n)
    float f = n / ((1.f + n) * sqrtf(fmaxf(n, 1e-30f)));
#pragma unroll
    for (int qq = 0; qq < 4; qq++)
        v4s[qq] = make_float4(f*s[qq*4+0], f*s[qq*4+1], f*s[qq*4+2], f*s[qq*4+3]);
    *clsp = n / (1.f + n);
}

#define XOR_RED4(a, off) do { \
    a.x += __shfl_xor_sync(0xffffffffu, a.x, off); \
    a.y += __shfl_xor_sync(0xffffffffu, a.y, off); \
    a.z += __shfl_xor_sync(0xffffffffu, a.z, off); \
    a.w += __shfl_xor_sync(0xffffffffu, a.w, off); } while (0)

// Phase-1 body: thread (g = route-in-chunk, q = out-quad) computes one quad.
#define PROJ_BODY(r) do { \
    float4 uu = __ldg(&ub[(r)]); \
    const float4* wp = Wb + (size_t)(r) * 16 + q; \
    float4 w0 = __ldg(wp);      float4 w1 = __ldg(wp + 4); \
    float4 w2 = __ldg(wp + 8);  float4 w3 = __ldg(wp + 12); \
    float4 o; \
    o.x = fmaf(uu.x,w0.x, fmaf(uu.y,w1.x, fmaf(uu.z,w2.x, uu.w*w3.x))); \
    o.y = fmaf(uu.x,w0.y, fmaf(uu.y,w1.y, fmaf(uu.z,w2.y, uu.w*w3.y))); \
    o.z = fmaf(uu.x,w0.z, fmaf(uu.y,w1.z, fmaf(uu.z,w2.z, uu.w*w3.z))); \
    o.w = fmaf(uu.x,w0.w, fmaf(uu.y,w1.w, fmaf(uu.z,w2.w, uu.w*w3.w))); \
    acc.x += o.x; acc.y += o.y; acc.z += o.z; acc.w += o.w; \
    plane[q * PSTRIDE + (r)] = o; } while (0)

__global__ void __launch_bounds__(256, 1) caps_fused_kernel(
    const float4* __restrict__ u4,   // u as float4: [b*NR + r]
    const float4* __restrict__ W4)   // W as float4: [(k*NR+r)*16 + i*4 + oq]
{
    extern __shared__ float sm[];
    float4* plane = (float4*)sm;
    float*  bs    = sm + OFF_BS;
    float4* red   = (float4*)(sm + OFF_RED);
    float*  zred  = sm + OFF_ZRED;
    float4* v4s   = (float4*)(sm + OFF_V);

    const int t = threadIdx.x;
    const int lane = t & 31, warp = t >> 5;
    const int bid = blockIdx.x;              // = b*2 + k
    const int b = bid >> 1, k = bid & 1;

    const float4* ub = u4 + (size_t)b * NR;
    const float4* Wb = W4 + (size_t)k * NR * 16;

    // --- Phase 1: projection into quad-planes, fused sweep-1 (uniform c) ---
    const int q = t & 3;                     // out-quad
    const int g = t >> 2;                    // route-in-chunk 0..63
    float4 acc = make_float4(0.f, 0.f, 0.f, 0.f);
#pragma unroll 2
    for (int c = 0; c < 36; c++) {
        int r = c * 64 + g;
        PROJ_BODY(r);
    }
    {   // tail chunk: 2336 = 36*64 + 32 -> only g < 32 valid
        int r = 36 * 64 + g;
        if (r < NR) PROJ_BODY(r);
    }

    // reduce acc across threads sharing q
    XOR_RED4(acc, 4); XOR_RED4(acc, 8); XOR_RED4(acc, 16);
    if (lane < 4) red[warp * 4 + lane] = acc;
    __syncthreads();
    if (warp == 0) {
        float4 a = red[lane];
        XOR_RED4(a, 4); XOR_RED4(a, 8); XOR_RED4(a, 16);
        if (lane < 4) red[lane] = a;
    }
    __syncthreads();
    if (t == 0) squash_store(red, v4s, sm + OFF_CLS, 1.f / (float)NR);
    __syncthreads();

    // --- Phase 2: two fused (b-update + softmax s-sweep) iterations ---
    // Thread-per-route: full 16-dot in registers, no inner-loop shuffles.
#pragma unroll
    for (int it = 0; it < 2; it++) {
        const float4 v0 = v4s[0], v1 = v4s[1], v2 = v4s[2], v3 = v4s[3];
        float4 a0 = make_float4(0,0,0,0), a1 = a0, a2 = a0, a3 = a0;
        float Z = 0.f;
        for (int r = t; r < NR; r += 256) {
            float4 x0 = plane[0*PSTRIDE + r];
            float4 x1 = plane[1*PSTRIDE + r];
            float4 x2 = plane[2*PSTRIDE + r];
            float4 x3 = plane[3*PSTRIDE + r];
            float d = x0.x*v0.x;
            d = fmaf(x0.y, v0.y, d); d = fmaf(x0.z, v0.z, d); d = fmaf(x0.w, v0.w, d);
            d = fmaf(x1.x, v1.x, d); d = fmaf(x1.y, v1.y, d);
            d = fmaf(x1.z, v1.z, d); d = fmaf(x1.w, v1.w, d);
            d = fmaf(x2.x, v2.x, d); d = fmaf(x2.y, v2.y, d);
            d = fmaf(x2.z, v2.z, d); d = fmaf(x2.w, v2.w, d);
            d = fmaf(x3.x, v3.x, d); d = fmaf(x3.y, v3.y, d);
            d = fmaf(x3.z, v3.z, d); d = fmaf(x3.w, v3.w, d);
            float bn;
            if (it == 0) { bn = d; bs[r] = bn; }
            else         { bn = bs[r] + d; }
            float e = __expf(bn);            // logits bounded, no max-shift
            Z += e;
            a0.x = fmaf(e, x0.x, a0.x); a0.y = fmaf(e, x0.y, a0.y);
            a0.z = fmaf(e, x0.z, a0.z); a0.w = fmaf(e, x0.w, a0.w);
            a1.x = fmaf(e, x1.x, a1.x); a1.y = fmaf(e, x1.y, a1.y);
            a1.z = fmaf(e, x1.z, a1.z); a1.w = fmaf(e, x1.w, a1.w);
            a2.x = fmaf(e, x2.x, a2.x); a2.y = fmaf(e, x2.y, a2.y);
            a2.z = fmaf(e, x2.z, a2.z); a2.w = fmaf(e, x2.w, a2.w);
            a3.x = fmaf(e, x3.x, a3.x); a3.y = fmaf(e, x3.y, a3.y);
            a3.z = fmaf(e, x3.z, a3.z); a3.w = fmaf(e, x3.w, a3.w);
        }
        // intra-warp reduce (each thread holds full 16-vec + Z)
        XOR_RED4(a0, 1); XOR_RED4(a0, 2); XOR_RED4(a0, 4); XOR_RED4(a0, 8); XOR_RED4(a0, 16);
        XOR_RED4(a1, 1); XOR_RED4(a1, 2); XOR_RED4(a1, 4); XOR_RED4(a1, 8); XOR_RED4(a1, 16);
        XOR_RED4(a2, 1); XOR_RED4(a2, 2); XOR_RED4(a2, 4); XOR_RED4(a2, 8); XOR_RED4(a2, 16);
        XOR_RED4(a3, 1); XOR_RED4(a3, 2); XOR_RED4(a3, 4); XOR_RED4(a3, 8); XOR_RED4(a3, 16);
        Z += __shfl_xor_sync(0xffffffffu, Z, 1);
        Z += __shfl_xor_sync(0xffffffffu, Z, 2);
        Z += __shfl_xor_sync(0xffffffffu, Z, 4);
        Z += __shfl_xor_sync(0xffffffffu, Z, 8);
        Z += __shfl_xor_sync(0xffffffffu, Z, 16);
        if (lane == 0) {
            red[warp*4+0] = a0; red[warp*4+1] = a1;
            red[warp*4+2] = a2; red[warp*4+3] = a3;
            zred[warp] = Z;
        }
        __syncthreads();
        if (warp == 0) {
            int w = lane & 7;                 // all 32 lanes converged
            float4 c0 = red[w*4+0], c1 = red[w*4+1], c2 = red[w*4+2], c3 = red[w*4+3];
            float Zt = zred[w];
            XOR_RED4(c0, 1); XOR_RED4(c0, 2); XOR_RED4(c0, 4);
            XOR_RED4(c1, 1); XOR_RED4(c1, 2); XOR_RED4(c1, 4);
            XOR_RED4(c2, 1); XOR_RED4(c2, 2); XOR_RED4(c2, 4);
            XOR_RED4(c3, 1); XOR_RED4(c3, 2); XOR_RED4(c3, 4);
            Zt += __shfl_xor_sync(0xffffffffu, Zt, 1);
            Zt += __shfl_xor_sync(0xffffffffu, Zt, 2);
            Zt += __shfl_xor_sync(0xffffffffu, Zt, 4);
            if (lane == 0) {
                float4 rr[4] = {c0, c1, c2, c3};
                squash_store(rr, v4s, sm + OFF_CLS, 1.f / Zt);
            }
        }
        __syncthreads();
    }

    if (t == 0) g_cls[bid] = sm[OFF_CLS];
}

// ---------------------------------------------------------------------------
// Final softmax over K=2 classes per batch
// ---------------------------------------------------------------------------
__global__ void caps_softmax_kernel(float* __restrict__ out)
{
    int b = blockIdx.x * blockDim.x + threadIdx.x;
    if (b < NB) {
        float c0 = g_cls[2*b], c1 = g_cls[2*b + 1];
        float m  = fmaxf(c0, c1);
        float e0 = expf(c0 - m), e1 = expf(c1 - m);
        float inv = 1.f / (e0 + e1);
        out[2*b]     = e0 * inv;
        out[2*b + 1] = e1 * inv;
    }
}

// ---------------------------------------------------------------------------
extern "C" void kernel_launch(void* const* d_in, const int* in_sizes, int n_in,
                              void* d_out, int out_size)
{
    const float4* u4 = (const float4*)d_in[0];   // u: [1024,2336,4] f32
    const float4* W4 = (const float4*)d_in[1];   // W: [2,2336,4,16] f32
    (void)in_sizes; (void)n_in; (void)out_size;

    cudaFuncSetAttribute(caps_fused_kernel,
                         cudaFuncAttributeMaxDynamicSharedMemorySize, SMEM_BYTES);

    caps_fused_kernel<<<NB * NK, 256, SMEM_BYTES>>>(u4, W4);
    caps_softmax_kernel<<<(NB + 255) / 256, 256>>>((float*)d_out);
}